// round 1
// baseline (speedup 1.0000x reference)
#include <cuda_runtime.h>
#include <cuda_fp16.h>

#define NB      1024
#define NN      256
#define ITERS   100
#define EPSD    1e-8f
#define THREADS 512

// smem layout (bytes):
//   Ks   : [0, 131072)              256*256 half
//   part : [131072, 147456)         16*256 float (Ktu partials)
//   u_s  : [147456, 148480)         256 float
//   v_s  : [148480, 149504)         256 float
//   a_s  : [149504, 150528)         256 float
//   b_s  : [150528, 151552)         256 float
//   red  : [151552, 151616)         16 float
#define SMEM_BYTES 151616

__device__ float g_batch_cost[NB];

// exp(-10*c) = 2^(c * -10*log2(e)), c in [0,1). deg-5 Taylor on f in [-0.5,0.5],
// rel err ~2.4e-6 (negligible vs fp16 storage of K).
__device__ __forceinline__ float fast_exp_n10(float c) {
    float t = c * (-14.426950408889634f);
    float r = rintf(t);
    float f = t - r;
    float p = 1.3333558146e-3f;
    p = fmaf(p, f, 9.6181291076e-3f);
    p = fmaf(p, f, 5.5504108664e-2f);
    p = fmaf(p, f, 2.4022650696e-1f);
    p = fmaf(p, f, 6.9314718056e-1f);
    p = fmaf(p, f, 1.0f);
    int e = (int)r;                       // r in [-15, 0], exact
    return __int_as_float(__float_as_int(p) + (e << 23));
}

// deterministic block reduce (fixed shuffle + warp-leader tree)
__device__ __forceinline__ float block_reduce(float val, float* red, int t) {
    #pragma unroll
    for (int o = 16; o > 0; o >>= 1)
        val += __shfl_xor_sync(0xffffffffu, val, o);
    if ((t & 31) == 0) red[t >> 5] = val;
    __syncthreads();
    if (t < 32) {
        float v2 = (t < (THREADS / 32)) ? red[t] : 0.0f;
        #pragma unroll
        for (int o = 8; o > 0; o >>= 1)
            v2 += __shfl_xor_sync(0xffffffffu, v2, o);
        if (t == 0) red[0] = v2;
    }
    __syncthreads();
    float out = red[0];
    __syncthreads();   // red reused by later reductions
    return out;
}

__global__ void __launch_bounds__(THREADS, 1)
sinkhorn_main(const float* __restrict__ Cmat,
              const float* __restrict__ mp,
              const float* __restrict__ mt) {
    extern __shared__ __align__(16) char smem_raw[];
    __half* Ks   = (__half*)smem_raw;
    float*  part = (float*)(smem_raw + 131072);
    float*  u_s  = (float*)(smem_raw + 147456);
    float*  v_s  = u_s + NN;
    float*  a_s  = v_s + NN;
    float*  b_s  = a_s + NN;
    float*  red  = b_s + NN;

    const int t = threadIdx.x;
    const int b = blockIdx.x;
    const float* Cb = Cmat + (size_t)b * (NN * NN);

    // ---- normalize masses ----
    float mpv = (t < NN) ? mp[b * NN + t] : 0.0f;
    float mtv = (t < NN) ? mt[b * NN + t] : 0.0f;
    float smp = block_reduce(mpv, red, t);
    float smt = block_reduce(mtv, red, t);
    if (t < NN) {
        a_s[t] = mpv / (smp + EPSD);
        b_s[t] = mtv / (smt + EPSD);
        u_s[t] = 1.0f;
    }

    // ---- build K = exp(-C/eps) in fp16 smem ----
    const float4* C4 = (const float4*)Cb;
    __half2* K2 = (__half2*)Ks;
    for (int i = t; i < (NN * NN / 4); i += THREADS) {
        float4 c4 = C4[i];
        __half2 h0 = __floats2half2_rn(fast_exp_n10(c4.x), fast_exp_n10(c4.y));
        __half2 h1 = __floats2half2_rn(fast_exp_n10(c4.z), fast_exp_n10(c4.w));
        K2[i * 2]     = h0;
        K2[i * 2 + 1] = h1;
    }
    __syncthreads();

    const int lane  = t & 31;
    const int w     = t >> 5;        // warp 0..15
    const int cbase = lane * 8;      // 8 consecutive columns per lane (16B LDS.128)
    const int chunk = w;             // 16-row chunk for Ktu

    // preload v-register slice addresses used by Kv
    for (int it = 0; it < ITERS; ++it) {
        // ===== Ktu partial: rows [chunk*16, +16), cols [cbase, +8) =====
        float acc[8] = {0.f,0.f,0.f,0.f,0.f,0.f,0.f,0.f};
        const int nb = chunk * 16;
        #pragma unroll
        for (int jj = 0; jj < 16; jj += 4) {
            const float4 u4 = *(const float4*)(u_s + nb + jj);
            const float uu[4] = {u4.x, u4.y, u4.z, u4.w};
            #pragma unroll
            for (int k = 0; k < 4; ++k) {
                const uint4 kv = *(const uint4*)(Ks + (nb + jj + k) * NN + cbase);
                const float2 f0 = __half22float2(*(const __half2*)&kv.x);
                const float2 f1 = __half22float2(*(const __half2*)&kv.y);
                const float2 f2 = __half22float2(*(const __half2*)&kv.z);
                const float2 f3 = __half22float2(*(const __half2*)&kv.w);
                acc[0] = fmaf(f0.x, uu[k], acc[0]);
                acc[1] = fmaf(f0.y, uu[k], acc[1]);
                acc[2] = fmaf(f1.x, uu[k], acc[2]);
                acc[3] = fmaf(f1.y, uu[k], acc[3]);
                acc[4] = fmaf(f2.x, uu[k], acc[4]);
                acc[5] = fmaf(f2.y, uu[k], acc[5]);
                acc[6] = fmaf(f3.x, uu[k], acc[6]);
                acc[7] = fmaf(f3.y, uu[k], acc[7]);
            }
        }
        {
            float4 p0 = make_float4(acc[0], acc[1], acc[2], acc[3]);
            float4 p1 = make_float4(acc[4], acc[5], acc[6], acc[7]);
            *(float4*)(part + chunk * NN + cbase)     = p0;
            *(float4*)(part + chunk * NN + cbase + 4) = p1;
        }
        __syncthreads();

        // ===== column sum over 16 chunks -> v =====
        if (t < NN) {
            float cs = 0.0f;
            #pragma unroll
            for (int ch = 0; ch < 16; ++ch) cs += part[ch * NN + t];
            v_s[t] = b_s[t] / (cs + EPSD);
        }
        __syncthreads();

        // ===== Kv: warp w rows [w*16, +16); lane dot-slice cols [cbase, +8) =====
        float vr[8];
        *(float4*)&vr[0] = *(const float4*)(v_s + cbase);
        *(float4*)&vr[4] = *(const float4*)(v_s + cbase + 4);
        #pragma unroll
        for (int j = 0; j < 16; ++j) {
            const int n = w * 16 + j;
            const uint4 kv = *(const uint4*)(Ks + n * NN + cbase);
            const float2 f0 = __half22float2(*(const __half2*)&kv.x);
            const float2 f1 = __half22float2(*(const __half2*)&kv.y);
            const float2 f2 = __half22float2(*(const __half2*)&kv.z);
            const float2 f3 = __half22float2(*(const __half2*)&kv.w);
            float s0 = f0.x * vr[0] + f0.y * vr[1];
            float s1 = f1.x * vr[2] + f1.y * vr[3];
            float s2 = f2.x * vr[4] + f2.y * vr[5];
            float s3 = f3.x * vr[6] + f3.y * vr[7];
            float s = (s0 + s1) + (s2 + s3);
            #pragma unroll
            for (int o = 16; o > 0; o >>= 1)
                s += __shfl_xor_sync(0xffffffffu, s, o);
            if (lane == 0) u_s[n] = a_s[n] / (s + EPSD);
        }
        __syncthreads();
    }

    // ===== final cost: sum u[n] * K[n,m] * v[m] * C[n,m] =====
    float csum = 0.0f;
    for (int i = t; i < (NN * NN / 4); i += THREADS) {
        const float4 c4 = C4[i];
        const int n  = i >> 6;            // 64 float4 per row
        const int m4 = (i & 63) * 4;
        const float un = u_s[n];
        const float2 k0 = __half22float2(K2[i * 2]);
        const float2 k1 = __half22float2(K2[i * 2 + 1]);
        const float4 vv = *(const float4*)(v_s + m4);
        float e = k0.x * vv.x * c4.x;
        e = fmaf(k0.y * vv.y, c4.y, e);
        e = fmaf(k1.x * vv.z, c4.z, e);
        e = fmaf(k1.y * vv.w, c4.w, e);
        csum = fmaf(un, e, csum);
    }
    float tot = block_reduce(csum, red, t);
    if (t == 0) g_batch_cost[b] = tot;
}

// deterministic final mean over batches
__global__ void sinkhorn_reduce(float* __restrict__ out) {
    __shared__ float sm[256];
    const int t = threadIdx.x;
    float s = 0.0f;
    #pragma unroll
    for (int i = t; i < NB; i += 256) s += g_batch_cost[i];
    sm[t] = s;
    __syncthreads();
    #pragma unroll
    for (int k = 128; k > 0; k >>= 1) {
        if (t < k) sm[t] += sm[t + k];
        __syncthreads();
    }
    if (t == 0) out[0] = sm[0] * (1.0f / (float)NB);
}

extern "C" void kernel_launch(void* const* d_in, const int* in_sizes, int n_in,
                              void* d_out, int out_size) {
    (void)in_sizes; (void)n_in; (void)out_size;
    const float* C  = (const float*)d_in[0];
    const float* mp = (const float*)d_in[1];
    const float* mt = (const float*)d_in[2];
    float* out = (float*)d_out;

    cudaFuncSetAttribute(sinkhorn_main,
                         cudaFuncAttributeMaxDynamicSharedMemorySize, SMEM_BYTES);
    sinkhorn_main<<<NB, THREADS, SMEM_BYTES>>>(C, mp, mt);
    sinkhorn_reduce<<<1, 256>>>(out);
}

// round 3
// speedup vs baseline: 1.8995x; 1.8995x over previous
#include <cuda_runtime.h>
#include <cuda_fp16.h>
#include <cstdint>

#define NB      1024
#define NN      256
#define ITERS   100
#define EPSD    1e-8f
#define THREADS 256

// padded K layout: 256 rows x 264 halves (528 B row stride)
#define ROWB    528

// smem byte offsets
#define OFF_KS   0                 // 256*264*2 = 135168
#define OFF_UH   135168            // 256 half
#define OFF_VH   135680            // 256 half
#define OFF_US   136192            // 256 f32
#define OFF_VS   137216
#define OFF_AS   138240
#define OFF_BS   139264
#define OFF_RED  140288            // 8 f32
#define SMEM_BYTES 140320

__device__ float g_batch_cost[NB];

__device__ __forceinline__ uint32_t smem_u32(const void* p) {
    uint32_t r;
    asm("{ .reg .u64 t; cvta.to.shared.u64 t, %1; cvt.u32.u64 %0, t; }" : "=r"(r) : "l"(p));
    return r;
}

__device__ __forceinline__ void ldsm_x4(uint32_t& r0, uint32_t& r1, uint32_t& r2,
                                        uint32_t& r3, uint32_t addr) {
    asm volatile("ldmatrix.sync.aligned.m8n8.x4.shared.b16 {%0,%1,%2,%3}, [%4];"
                 : "=r"(r0), "=r"(r1), "=r"(r2), "=r"(r3) : "r"(addr));
}

__device__ __forceinline__ void ldsm_x2_trans(uint32_t& r0, uint32_t& r1, uint32_t addr) {
    asm volatile("ldmatrix.sync.aligned.m8n8.x2.trans.shared.b16 {%0,%1}, [%2];"
                 : "=r"(r0), "=r"(r1) : "r"(addr));
}

__device__ __forceinline__ void mma16816(float c[4], uint32_t a0, uint32_t a1,
                                         uint32_t a2, uint32_t a3,
                                         uint32_t b0, uint32_t b1) {
    asm volatile(
        "mma.sync.aligned.m16n8k16.row.col.f32.f16.f16.f32 "
        "{%0,%1,%2,%3}, {%4,%5,%6,%7}, {%8,%9}, {%0,%1,%2,%3};"
        : "+f"(c[0]), "+f"(c[1]), "+f"(c[2]), "+f"(c[3])
        : "r"(a0), "r"(a1), "r"(a2), "r"(a3), "r"(b0), "r"(b1));
}

// exp(-10*c) = 2^(-10*log2e*c), deg-5 poly, rel err ~2.4e-6
__device__ __forceinline__ float fast_exp_n10(float c) {
    float t = c * (-14.426950408889634f);
    float r = rintf(t);
    float f = t - r;
    float p = 1.3333558146e-3f;
    p = fmaf(p, f, 9.6181291076e-3f);
    p = fmaf(p, f, 5.5504108664e-2f);
    p = fmaf(p, f, 2.4022650696e-1f);
    p = fmaf(p, f, 6.9314718056e-1f);
    p = fmaf(p, f, 1.0f);
    return __int_as_float(__float_as_int(p) + (((int)r) << 23));
}

__device__ __forceinline__ float block_reduce256(float val, float* red, int t) {
    #pragma unroll
    for (int o = 16; o > 0; o >>= 1)
        val += __shfl_xor_sync(0xffffffffu, val, o);
    if ((t & 31) == 0) red[t >> 5] = val;
    __syncthreads();
    if (t < 32) {
        float v2 = (t < 8) ? red[t] : 0.0f;
        #pragma unroll
        for (int o = 4; o > 0; o >>= 1)
            v2 += __shfl_xor_sync(0xffffffffu, v2, o);
        if (t == 0) red[0] = v2;
    }
    __syncthreads();
    float out = red[0];
    __syncthreads();
    return out;
}

__global__ void __launch_bounds__(THREADS, 1)
sinkhorn_main(const float* __restrict__ Cmat,
              const float* __restrict__ mp,
              const float* __restrict__ mt) {
    extern __shared__ __align__(16) char A0[];
    __half* uh  = (__half*)(A0 + OFF_UH);
    __half* vh  = (__half*)(A0 + OFF_VH);
    float*  u_s = (float*)(A0 + OFF_US);
    float*  v_s = (float*)(A0 + OFF_VS);
    float*  a_s = (float*)(A0 + OFF_AS);
    float*  b_s = (float*)(A0 + OFF_BS);
    float*  red = (float*)(A0 + OFF_RED);

    const int t    = threadIdx.x;
    const int lane = t & 31;
    const int w    = t >> 5;
    const int b    = blockIdx.x;
    const float* Cb = Cmat + (size_t)b * (NN * NN);
    const uint32_t ks_base = smem_u32(A0 + OFF_KS);

    // ---- build K = exp(-C/eps) fp16 into padded row-major smem ----
    {
        const float4* C4 = (const float4*)Cb;
        for (int i = t; i < (NN * NN / 4); i += THREADS) {
            float4 c4 = C4[i];
            int n = i >> 6;
            int m = (i & 63) << 2;
            __half2 h0 = __floats2half2_rn(fast_exp_n10(c4.x), fast_exp_n10(c4.y));
            __half2 h1 = __floats2half2_rn(fast_exp_n10(c4.z), fast_exp_n10(c4.w));
            uint2 kk;
            kk.x = *(uint32_t*)&h0;
            kk.y = *(uint32_t*)&h1;
            *(uint2*)(A0 + OFF_KS + n * ROWB + m * 2) = kk;
        }
    }

    // ---- normalize masses (block_reduce syncs also cover K writes) ----
    float mpv = mp[b * NN + t];
    float mtv = mt[b * NN + t];
    float smp = block_reduce256(mpv, red, t);
    float smt = block_reduce256(mtv, red, t);
    a_s[t] = mpv / (smp + EPSD);
    b_s[t] = mtv / (smt + EPSD);
    u_s[t] = 1.0f;
    uh[t]  = __float2half_rn(1.0f);
    __syncthreads();

    // ---- one-time: load K^T B-fragments into registers ----
    // kb[(kc*4+mt)*2 + {0,1}]: B-frag (k = n in [kc*16,+16), col = m in [w*32+mt*8,+8))
    uint32_t kb[128];
    {
        #pragma unroll
        for (int kc = 0; kc < 16; ++kc) {
            #pragma unroll
            for (int mt = 0; mt < 4; ++mt) {
                uint32_t addr = ks_base + (uint32_t)(kc * 16 + (lane & 15)) * ROWB
                              + (uint32_t)(w * 32 + mt * 8) * 2;
                ldsm_x2_trans(kb[(kc * 4 + mt) * 2], kb[(kc * 4 + mt) * 2 + 1], addr);
            }
        }
    }

    const int lm2 = (lane & 3) * 2;   // k-pair base within chunk

    for (int it = 0; it < ITERS; ++it) {
        // ===== Phase A: Ktu[m] = sum_n K[n,m]*u[n]; K^T frags in regs =====
        float acc[4][4] = {{0,0,0,0},{0,0,0,0},{0,0,0,0},{0,0,0,0}};
        #pragma unroll
        for (int kc = 0; kc < 16; ++kc) {
            uint32_t a01 = *(const uint32_t*)(uh + kc * 16 + lm2);
            uint32_t a23 = *(const uint32_t*)(uh + kc * 16 + lm2 + 8);
            #pragma unroll
            for (int mt = 0; mt < 4; ++mt)
                mma16816(acc[mt], a01, a01, a23, a23,
                         kb[(kc * 4 + mt) * 2], kb[(kc * 4 + mt) * 2 + 1]);
        }
        if (lane < 4) {
            #pragma unroll
            for (int mt = 0; mt < 4; ++mt) {
                int m = w * 32 + mt * 8 + lane * 2;
                float v0 = b_s[m]     / (acc[mt][0] + EPSD);
                float v1 = b_s[m + 1] / (acc[mt][1] + EPSD);
                v_s[m]     = v0;
                v_s[m + 1] = v1;
                *(__half2*)(vh + m) = __floats2half2_rn(v0, v1);
            }
        }
        __syncthreads();

        // ===== Phase B: Kv[n] = sum_m K[n,m]*v[m]; A via ldmatrix =====
        float accB[2][4] = {{0,0,0,0},{0,0,0,0}};
        const uint32_t lrow = (uint32_t)(lane & 15) * ROWB + ((lane & 16) ? 16u : 0u);
        #pragma unroll
        for (int kc = 0; kc < 16; ++kc) {
            uint32_t b0 = *(const uint32_t*)(vh + kc * 16 + lm2);
            uint32_t b1 = *(const uint32_t*)(vh + kc * 16 + lm2 + 8);
            #pragma unroll
            for (int s = 0; s < 2; ++s) {
                uint32_t addr = ks_base + (uint32_t)(w * 2 + s) * (16 * ROWB)
                              + lrow + (uint32_t)kc * 32;
                uint32_t A0r, A1r, A2r, A3r;
                ldsm_x4(A0r, A1r, A2r, A3r, addr);
                mma16816(accB[s], A0r, A1r, A2r, A3r, b0, b1);
            }
        }
        if ((lane & 3) == 0) {
            #pragma unroll
            for (int s = 0; s < 2; ++s) {
                int n0 = (w * 2 + s) * 16 + (lane >> 2);
                float u0 = a_s[n0]     / (accB[s][0] + EPSD);
                float u8 = a_s[n0 + 8] / (accB[s][2] + EPSD);
                u_s[n0]     = u0;
                u_s[n0 + 8] = u8;
                uh[n0]     = __float2half_rn(u0);
                uh[n0 + 8] = __float2half_rn(u8);
            }
        }
        __syncthreads();
    }

    // ===== final cost: sum_nm u[n]*K[n,m]*v[m]*C[n,m] =====
    float csum = 0.0f;
    {
        const float4* C4 = (const float4*)Cb;
        for (int i = t; i < (NN * NN / 4); i += THREADS) {
            float4 c4 = C4[i];
            int n = i >> 6;
            int m = (i & 63) << 2;
            uint2 kk = *(const uint2*)(A0 + OFF_KS + n * ROWB + m * 2);
            float2 f0 = __half22float2(*(__half2*)&kk.x);
            float2 f1 = __half22float2(*(__half2*)&kk.y);
            float4 vv = *(const float4*)(v_s + m);
            float un = u_s[n];
            float e = f0.x * vv.x * c4.x;
            e = fmaf(f0.y * vv.y, c4.y, e);
            e = fmaf(f1.x * vv.z, c4.z, e);
            e = fmaf(f1.y * vv.w, c4.w, e);
            csum = fmaf(un, e, csum);
        }
    }
    float tot = block_reduce256(csum, red, t);
    if (t == 0) g_batch_cost[b] = tot;
}

// deterministic final mean over batches
__global__ void sinkhorn_reduce(float* __restrict__ out) {
    __shared__ float sm[256];
    const int t = threadIdx.x;
    float s = 0.0f;
    #pragma unroll
    for (int i = t; i < NB; i += 256) s += g_batch_cost[i];
    sm[t] = s;
    __syncthreads();
    #pragma unroll
    for (int k = 128; k > 0; k >>= 1) {
        if (t < k) sm[t] += sm[t + k];
        __syncthreads();
    }
    if (t == 0) out[0] = sm[0] * (1.0f / (float)NB);
}

extern "C" void kernel_launch(void* const* d_in, const int* in_sizes, int n_in,
                              void* d_out, int out_size) {
    (void)in_sizes; (void)n_in; (void)out_size;
    const float* C  = (const float*)d_in[0];
    const float* mp = (const float*)d_in[1];
    const float* mt = (const float*)d_in[2];
    float* out = (float*)d_out;

    cudaFuncSetAttribute(sinkhorn_main,
                         cudaFuncAttributeMaxDynamicSharedMemorySize, SMEM_BYTES);
    sinkhorn_main<<<NB, THREADS, SMEM_BYTES>>>(C, mp, mt);
    sinkhorn_reduce<<<1, 256>>>(out);
}

// round 4
// speedup vs baseline: 2.2445x; 1.1816x over previous
#include <cuda_runtime.h>
#include <cuda_fp16.h>
#include <cstdint>

#define NB      1024
#define NN      256
#define ITERS   100
#define EPSD    1e-8f
#define THREADS 512

// padded K layout: 256 rows x 264 halves (528 B row stride)
#define ROWB    528

// smem byte offsets
#define OFF_KS   0                 // 256*264*2 = 135168
#define OFF_UH   135168            // 256 half
#define OFF_VH   135680            // 256 half
#define OFF_US   136192            // 256 f32
#define OFF_VS   137216
#define OFF_AS   138240
#define OFF_BS   139264
#define OFF_RED  140288            // 16 f32
#define SMEM_BYTES 140352

__device__ float g_batch_cost[NB];

__device__ __forceinline__ uint32_t smem_u32(const void* p) {
    uint32_t r;
    asm("{ .reg .u64 t; cvta.to.shared.u64 t, %1; cvt.u32.u64 %0, t; }" : "=r"(r) : "l"(p));
    return r;
}

__device__ __forceinline__ void ldsm_x4(uint32_t& r0, uint32_t& r1, uint32_t& r2,
                                        uint32_t& r3, uint32_t addr) {
    asm volatile("ldmatrix.sync.aligned.m8n8.x4.shared.b16 {%0,%1,%2,%3}, [%4];"
                 : "=r"(r0), "=r"(r1), "=r"(r2), "=r"(r3) : "r"(addr));
}

__device__ __forceinline__ void ldsm_x2_trans(uint32_t& r0, uint32_t& r1, uint32_t addr) {
    asm volatile("ldmatrix.sync.aligned.m8n8.x2.trans.shared.b16 {%0,%1}, [%2];"
                 : "=r"(r0), "=r"(r1) : "r"(addr));
}

__device__ __forceinline__ void mma16816(float c[4], uint32_t a0, uint32_t a1,
                                         uint32_t a2, uint32_t a3,
                                         uint32_t b0, uint32_t b1) {
    asm volatile(
        "mma.sync.aligned.m16n8k16.row.col.f32.f16.f16.f32 "
        "{%0,%1,%2,%3}, {%4,%5,%6,%7}, {%8,%9}, {%0,%1,%2,%3};"
        : "+f"(c[0]), "+f"(c[1]), "+f"(c[2]), "+f"(c[3])
        : "r"(a0), "r"(a1), "r"(a2), "r"(a3), "r"(b0), "r"(b1));
}

// exp(-10*c) = 2^(-10*log2e*c), deg-5 poly, rel err ~2.4e-6
__device__ __forceinline__ float fast_exp_n10(float c) {
    float t = c * (-14.426950408889634f);
    float r = rintf(t);
    float f = t - r;
    float p = 1.3333558146e-3f;
    p = fmaf(p, f, 9.6181291076e-3f);
    p = fmaf(p, f, 5.5504108664e-2f);
    p = fmaf(p, f, 2.4022650696e-1f);
    p = fmaf(p, f, 6.9314718056e-1f);
    p = fmaf(p, f, 1.0f);
    return __int_as_float(__float_as_int(p) + (((int)r) << 23));
}

__device__ __forceinline__ float block_reduce(float val, float* red, int t) {
    #pragma unroll
    for (int o = 16; o > 0; o >>= 1)
        val += __shfl_xor_sync(0xffffffffu, val, o);
    if ((t & 31) == 0) red[t >> 5] = val;
    __syncthreads();
    if (t < 32) {
        float v2 = (t < (THREADS / 32)) ? red[t] : 0.0f;
        #pragma unroll
        for (int o = 8; o > 0; o >>= 1)
            v2 += __shfl_xor_sync(0xffffffffu, v2, o);
        if (t == 0) red[0] = v2;
    }
    __syncthreads();
    float out = red[0];
    __syncthreads();
    return out;
}

__global__ void __launch_bounds__(THREADS, 1)
sinkhorn_main(const float* __restrict__ Cmat,
              const float* __restrict__ mp,
              const float* __restrict__ mt) {
    extern __shared__ __align__(16) char A0[];
    __half* uh  = (__half*)(A0 + OFF_UH);
    __half* vh  = (__half*)(A0 + OFF_VH);
    float*  u_s = (float*)(A0 + OFF_US);
    float*  v_s = (float*)(A0 + OFF_VS);
    float*  a_s = (float*)(A0 + OFF_AS);
    float*  b_s = (float*)(A0 + OFF_BS);
    float*  red = (float*)(A0 + OFF_RED);

    const int t    = threadIdx.x;
    const int lane = t & 31;
    const int w    = t >> 5;              // warp 0..15
    const int b    = blockIdx.x;
    const float* Cb = Cmat + (size_t)b * (NN * NN);
    const uint32_t ks_base = smem_u32(A0 + OFF_KS);

    // ---- build K = exp(-C/eps) fp16 into padded row-major smem ----
    {
        const float4* C4 = (const float4*)Cb;
        for (int i = t; i < (NN * NN / 4); i += THREADS) {
            float4 c4 = C4[i];
            int n = i >> 6;
            int m = (i & 63) << 2;
            __half2 h0 = __floats2half2_rn(fast_exp_n10(c4.x), fast_exp_n10(c4.y));
            __half2 h1 = __floats2half2_rn(fast_exp_n10(c4.z), fast_exp_n10(c4.w));
            uint2 kk;
            kk.x = *(uint32_t*)&h0;
            kk.y = *(uint32_t*)&h1;
            *(uint2*)(A0 + OFF_KS + n * ROWB + m * 2) = kk;
        }
    }

    // ---- normalize masses (block_reduce syncs also cover K writes) ----
    float mpv = (t < NN) ? mp[b * NN + t] : 0.0f;
    float mtv = (t < NN) ? mt[b * NN + t] : 0.0f;
    float smp = block_reduce(mpv, red, t);
    float smt = block_reduce(mtv, red, t);
    if (t < NN) {
        a_s[t] = mpv / (smp + EPSD);
        b_s[t] = mtv / (smt + EPSD);
        u_s[t] = 1.0f;
        uh[t]  = __float2half_rn(1.0f);
    }
    __syncthreads();

    // ---- one-time: K^T B-fragments (k = n) into registers ----
    // warp w owns m-cols [w*16, w*16+16): kb[(kc*2+mt)*2 + {0,1}]
    uint32_t kb[64];
    {
        #pragma unroll
        for (int kc = 0; kc < 16; ++kc) {
            #pragma unroll
            for (int mtile = 0; mtile < 2; ++mtile) {
                uint32_t addr = ks_base + (uint32_t)(kc * 16 + (lane & 15)) * ROWB
                              + (uint32_t)(w * 16 + mtile * 8) * 2;
                ldsm_x2_trans(kb[(kc * 2 + mtile) * 2], kb[(kc * 2 + mtile) * 2 + 1], addr);
            }
        }
    }

    const int lm2 = (lane & 3) * 2;   // k-pair base within 16-chunk
    const uint32_t lrowB = ks_base + (uint32_t)(w * 16 + (lane & 15)) * ROWB
                         + ((lane & 16) ? 16u : 0u);

    for (int it = 0; it < ITERS; ++it) {
        // ===== Phase A: Ktu[m] = sum_n K[n,m]*u[n]; K^T frags in regs =====
        // two k-half accumulator sets -> 4 independent HMMA chains of depth 8
        float accA[2][2][4] = {{{0,0,0,0},{0,0,0,0}},{{0,0,0,0},{0,0,0,0}}};
        #pragma unroll
        for (int kc = 0; kc < 16; ++kc) {
            const int kh = kc >> 3;
            uint32_t a01 = *(const uint32_t*)(uh + kc * 16 + lm2);
            uint32_t a23 = *(const uint32_t*)(uh + kc * 16 + lm2 + 8);
            mma16816(accA[kh][0], a01, a01, a23, a23, kb[(kc * 2) * 2],     kb[(kc * 2) * 2 + 1]);
            mma16816(accA[kh][1], a01, a01, a23, a23, kb[(kc * 2 + 1) * 2], kb[(kc * 2 + 1) * 2 + 1]);
        }
        if (lane < 4) {
            #pragma unroll
            for (int mtile = 0; mtile < 2; ++mtile) {
                int m = w * 16 + mtile * 8 + lane * 2;
                float s0 = accA[0][mtile][0] + accA[1][mtile][0];
                float s1 = accA[0][mtile][1] + accA[1][mtile][1];
                float v0 = __fdividef(b_s[m],     s0 + EPSD);
                float v1 = __fdividef(b_s[m + 1], s1 + EPSD);
                v_s[m]     = v0;
                v_s[m + 1] = v1;
                *(__half2*)(vh + m) = __floats2half2_rn(v0, v1);
            }
        }
        __syncthreads();

        // ===== Phase B: Kv[n] = sum_m K[n,m]*v[m]; warp w rows [w*16,+16) =====
        float accB[2][4] = {{0,0,0,0},{0,0,0,0}};
        #pragma unroll
        for (int kc = 0; kc < 16; ++kc) {
            uint32_t b0 = *(const uint32_t*)(vh + kc * 16 + lm2);
            uint32_t b1 = *(const uint32_t*)(vh + kc * 16 + lm2 + 8);
            uint32_t A0r, A1r, A2r, A3r;
            ldsm_x4(A0r, A1r, A2r, A3r, lrowB + (uint32_t)kc * 32);
            mma16816(accB[kc & 1], A0r, A1r, A2r, A3r, b0, b1);
        }
        if ((lane & 3) == 0) {
            int n0 = w * 16 + (lane >> 2);
            float s0 = accB[0][0] + accB[1][0];
            float s2 = accB[0][2] + accB[1][2];
            float u0 = __fdividef(a_s[n0],     s0 + EPSD);
            float u8 = __fdividef(a_s[n0 + 8], s2 + EPSD);
            u_s[n0]     = u0;
            u_s[n0 + 8] = u8;
            uh[n0]     = __float2half_rn(u0);
            uh[n0 + 8] = __float2half_rn(u8);
        }
        __syncthreads();
    }

    // ===== final cost: sum_nm u[n]*K[n,m]*v[m]*C[n,m] =====
    float csum = 0.0f;
    {
        const float4* C4 = (const float4*)Cb;
        for (int i = t; i < (NN * NN / 4); i += THREADS) {
            float4 c4 = C4[i];
            int n = i >> 6;
            int m = (i & 63) << 2;
            uint2 kk = *(const uint2*)(A0 + OFF_KS + n * ROWB + m * 2);
            float2 f0 = __half22float2(*(__half2*)&kk.x);
            float2 f1 = __half22float2(*(__half2*)&kk.y);
            float4 vv = *(const float4*)(v_s + m);
            float un = u_s[n];
            float e = f0.x * vv.x * c4.x;
            e = fmaf(f0.y * vv.y, c4.y, e);
            e = fmaf(f1.x * vv.z, c4.z, e);
            e = fmaf(f1.y * vv.w, c4.w, e);
            csum = fmaf(un, e, csum);
        }
    }
    float tot = block_reduce(csum, red, t);
    if (t == 0) g_batch_cost[b] = tot;
}

// deterministic final mean over batches
__global__ void sinkhorn_reduce(float* __restrict__ out) {
    __shared__ float sm[256];
    const int t = threadIdx.x;
    float s = 0.0f;
    #pragma unroll
    for (int i = t; i < NB; i += 256) s += g_batch_cost[i];
    sm[t] = s;
    __syncthreads();
    #pragma unroll
    for (int k = 128; k > 0; k >>= 1) {
        if (t < k) sm[t] += sm[t + k];
        __syncthreads();
    }
    if (t == 0) out[0] = sm[0] * (1.0f / (float)NB);
}

extern "C" void kernel_launch(void* const* d_in, const int* in_sizes, int n_in,
                              void* d_out, int out_size) {
    (void)in_sizes; (void)n_in; (void)out_size;
    const float* C  = (const float*)d_in[0];
    const float* mp = (const float*)d_in[1];
    const float* mt = (const float*)d_in[2];
    float* out = (float*)d_out;

    cudaFuncSetAttribute(sinkhorn_main,
                         cudaFuncAttributeMaxDynamicSharedMemorySize, SMEM_BYTES);
    sinkhorn_main<<<NB, THREADS, SMEM_BYTES>>>(C, mp, mt);
    sinkhorn_reduce<<<1, 256>>>(out);
}